// round 2
// baseline (speedup 1.0000x reference)
#include <cuda_runtime.h>
#include <cuda_bf16.h>

typedef unsigned long long ull;

#define Bq   128
#define Tq   40
#define HIDq 512
#define VOCq 10000

// ---------------- scratch (device globals; no allocation) ----------------
__device__ float g_P[3][Tq * Bq * HIDq];   // precomputed x-projections per gate (u,r,c), layer 0
__device__ float g_C[3][Bq * HIDq];        // cnn projection + bias per gate, layer 0
__device__ float g_H0[Bq * HIDq];
__device__ float g_H1[Bq * HIDq];
__device__ float g_Z0[Bq * HIDq];
__device__ float g_RH0[Bq * HIDq];
__device__ float g_Z1[Bq * HIDq];
__device__ float g_RH1[Bq * HIDq];
__device__ float g_H1seq[Tq * Bq * HIDq];

// ---------------- packed f32x2 helpers (Blackwell FFMA2) ----------------
__device__ __forceinline__ ull pk2(float x, float y) {
    ull r; asm("mov.b64 %0, {%1,%2};" : "=l"(r) : "f"(x), "f"(y)); return r;
}
__device__ __forceinline__ void upk2(ull v, float &x, float &y) {
    asm("mov.b64 {%0,%1}, %2;" : "=f"(x), "=f"(y) : "l"(v));
}
__device__ __forceinline__ void fma2(ull &c, ull a, ull b) {
    asm("fma.rn.f32x2 %0, %1, %2, %3;" : "=l"(c) : "l"(a), "l"(b), "l"(c));
}

// ---------------- generic double-buffered SGEMM core ----------------
// C[BM,BN] tile = sum_k aload(k,mm) * wload(k,nn), epilogue epi(mi,nj,val).
// A loads are K-contiguous (coalesced for row-major A), W loads N-contiguous.
template<int BM, int BN, int BK, int TM, int TN, class AF, class WF, class EF>
__device__ __forceinline__ void gemm_core(int K, AF aload, WF wload, EF epi)
{
    constexpr int NT      = BN / TN;
    constexpr int MT      = BM / TM;
    constexpr int THREADS = NT * MT;
    constexpr int TN2     = TN / 2;
    constexpr int ALD     = BM * BK / THREADS;
    constexpr int WLD     = BK * BN / THREADS;
    constexpr int AS      = BM + 1;   // pad to avoid STS bank conflicts

    __shared__ float As[2][BK][AS];
    __shared__ __align__(16) float Ws[2][BK][BN];

    const int tid = threadIdx.x;
    const int tx  = tid % NT;
    const int ty  = tid / NT;

    ull acc[TM][TN2];
#pragma unroll
    for (int i = 0; i < TM; i++)
#pragma unroll
        for (int j = 0; j < TN2; j++) acc[i][j] = 0ull;

    // prologue: stage k-block 0
#pragma unroll
    for (int j = 0; j < ALD; j++) {
        int idx = tid + j * THREADS;
        As[0][idx % BK][idx / BK] = aload(idx % BK, idx / BK);
    }
#pragma unroll
    for (int j = 0; j < WLD; j++) {
        int idx = tid + j * THREADS;
        Ws[0][idx / BN][idx % BN] = wload(idx / BN, idx % BN);
    }
    __syncthreads();

    const int niter = K / BK;
    for (int it = 0; it < niter; ++it) {
        float ra[ALD], rw[WLD];
        const int kn = (it + 1) * BK;
        if (it + 1 < niter) {   // register prefetch: LDGs in flight during compute
#pragma unroll
            for (int j = 0; j < ALD; j++) {
                int idx = tid + j * THREADS;
                ra[j] = aload(kn + idx % BK, idx / BK);
            }
#pragma unroll
            for (int j = 0; j < WLD; j++) {
                int idx = tid + j * THREADS;
                rw[j] = wload(kn + idx / BN, idx % BN);
            }
        }
        const int cur = it & 1;
#pragma unroll
        for (int kk = 0; kk < BK; kk++) {
            float a[TM]; ull b[TN2];
            const ull *wp = reinterpret_cast<const ull *>(&Ws[cur][kk][tx * TN]);
#pragma unroll
            for (int j = 0; j < TN2; j++) b[j] = wp[j];
#pragma unroll
            for (int i = 0; i < TM; i++) a[i] = As[cur][kk][ty * TM + i];
#pragma unroll
            for (int i = 0; i < TM; i++) {
                ull a2 = pk2(a[i], a[i]);
#pragma unroll
                for (int j = 0; j < TN2; j++) fma2(acc[i][j], a2, b[j]);
            }
        }
        if (it + 1 < niter) {
            const int nxt = cur ^ 1;
#pragma unroll
            for (int j = 0; j < ALD; j++) {
                int idx = tid + j * THREADS;
                As[nxt][idx % BK][idx / BK] = ra[j];
            }
#pragma unroll
            for (int j = 0; j < WLD; j++) {
                int idx = tid + j * THREADS;
                Ws[nxt][idx / BN][idx % BN] = rw[j];
            }
            __syncthreads();
        }
    }

#pragma unroll
    for (int i = 0; i < TM; i++)
#pragma unroll
        for (int j = 0; j < TN2; j++) {
            float lo, hi; upk2(acc[i][j], lo, hi);
            epi(ty * TM + i, tx * TN + 2 * j,     lo);
            epi(ty * TM + i, tx * TN + 2 * j + 1, hi);
        }
}

__device__ __forceinline__ float sigm(float x) { return 1.f / (1.f + expf(-x)); }

// ---------------- kernels ----------------

__global__ void k_init() {
    int i = blockIdx.x * blockDim.x + threadIdx.x;
    if (i < Bq * HIDq) { g_H0[i] = 0.f; g_H1[i] = 0.f; }
}

// C_g = cnn @ Wg0[1024:1536] + b_g0    (time-invariant part of layer-0 input proj)
__global__ void k_cnn(const float *cnn, const float *wu, const float *wr, const float *wc,
                      const float *bu, const float *br, const float *bc)
{
    int g = blockIdx.z;
    const float *W    = (g == 0 ? wu : g == 1 ? wr : wc) + 1024 * HIDq;
    const float *bias = (g == 0 ? bu : g == 1 ? br : bc);
    int m0 = blockIdx.y * 64, n0 = blockIdx.x * 64;
    float *Cout = g_C[g];
    gemm_core<64, 64, 16, 4, 8>(512,
        [&](int k, int mm) { return cnn[(m0 + mm) * HIDq + k]; },
        [&](int k, int nn) { return W[k * HIDq + n0 + nn]; },
        [&](int mi, int nj, float v) { Cout[(m0 + mi) * HIDq + n0 + nj] = v + bias[n0 + nj]; });
}

// P_g[t] = emb[tokens[:,t]] @ Wg0[512:1024] + C_g   (all t, all gates, parallel)
__global__ void k_embed(const int *tokens, const float *emb,
                        const float *wu, const float *wr, const float *wc)
{
    __shared__ int rowtok[128];
    int g = blockIdx.z, t = blockIdx.y, n0 = blockIdx.x * 64;
    if (threadIdx.x < 128) rowtok[threadIdx.x] = tokens[threadIdx.x * Tq + t];
    __syncthreads();
    const float *W  = (g == 0 ? wu : g == 1 ? wr : wc) + 512 * HIDq;
    const float *Cg = g_C[g];
    float *Pg = g_P[g] + t * Bq * HIDq;
    gemm_core<128, 64, 16, 8, 8>(512,
        [&](int k, int mm) { return emb[(long)rowtok[mm] * HIDq + k]; },
        [&](int k, int nn) { return W[k * HIDq + n0 + nn]; },
        [&](int mi, int nj, float v) { Pg[mi * HIDq + n0 + nj] = v + Cg[mi * HIDq + n0 + nj]; });
}

// layer-0 update/reset gates: z0 = sig(P_u + h0@Wu_h), rh0 = sig(P_r + h0@Wr_h)*h0
__global__ void k_zr0(int t, const float *wu, const float *wr)
{
    int m0 = blockIdx.y * 32;
    int ng = blockIdx.x * 32;
    int gate = ng >= 512;
    int n0 = gate ? ng - 512 : ng;
    const float *W = gate ? wr : wu;                 // h-part = rows 0:512
    const float *P = g_P[gate] + t * Bq * HIDq;
    gemm_core<32, 32, 32, 4, 2>(512,
        [&](int k, int mm) { return g_H0[(m0 + mm) * HIDq + k]; },
        [&](int k, int nn) { return W[k * HIDq + n0 + nn]; },
        [&](int mi, int nj, float v) {
            int idx = (m0 + mi) * HIDq + n0 + nj;
            float s = sigm(v + P[idx]);
            if (gate == 0) g_Z0[idx] = s;
            else           g_RH0[idx] = s * g_H0[idx];
        });
}

// layer-0 candidate + state update: h0 = z0*h0 + (1-z0)*tanh(P_c + rh0@Wc_h)
__global__ void k_h0(int t, const float *wc)
{
    int m0 = blockIdx.y * 32, n0 = blockIdx.x * 32;
    const float *P = g_P[2] + t * Bq * HIDq;
    gemm_core<32, 32, 32, 4, 2>(512,
        [&](int k, int mm) { return g_RH0[(m0 + mm) * HIDq + k]; },
        [&](int k, int nn) { return wc[k * HIDq + n0 + nn]; },
        [&](int mi, int nj, float v) {
            int idx = (m0 + mi) * HIDq + n0 + nj;
            float hh = tanhf(v + P[idx]);
            float z  = g_Z0[idx];
            g_H0[idx] = z * g_H0[idx] + (1.f - z) * hh;
        });
}

// layer-1 update/reset gates: inp = [h1 | h0] (K=1024)
__global__ void k_zr1(const float *wu, const float *wr, const float *bu, const float *br)
{
    int m0 = blockIdx.y * 32, ng = blockIdx.x * 32;
    int gate = ng >= 512;
    int n0 = gate ? ng - 512 : ng;
    const float *W    = gate ? wr : wu;
    const float *bias = gate ? br : bu;
    gemm_core<32, 32, 32, 4, 2>(1024,
        [&](int k, int mm) {
            int m = m0 + mm;
            return (k < 512) ? g_H1[m * HIDq + k] : g_H0[m * HIDq + k - 512];
        },
        [&](int k, int nn) { return W[k * HIDq + n0 + nn]; },
        [&](int mi, int nj, float v) {
            int idx = (m0 + mi) * HIDq + n0 + nj;
            float s = sigm(v + bias[n0 + nj]);
            if (!gate) g_Z1[idx] = s;
            else       g_RH1[idx] = s * g_H1[idx];
        });
}

// layer-1 candidate + state update, also records h1 into the sequence buffer
__global__ void k_h1(int t, const float *wc, const float *bc)
{
    int m0 = blockIdx.y * 32, n0 = blockIdx.x * 32;
    gemm_core<32, 32, 32, 4, 2>(1024,
        [&](int k, int mm) {
            int m = m0 + mm;
            return (k < 512) ? g_RH1[m * HIDq + k] : g_H0[m * HIDq + k - 512];
        },
        [&](int k, int nn) { return wc[k * HIDq + n0 + nn]; },
        [&](int mi, int nj, float v) {
            int idx = (m0 + mi) * HIDq + n0 + nj;
            float hh = tanhf(v + bc[n0 + nj]);
            float z  = g_Z1[idx];
            float hn = z * g_H1[idx] + (1.f - z) * hh;
            g_H1[idx] = hn;
            g_H1seq[t * Bq * HIDq + idx] = hn;
        });
}

// logits[b,t,:] = h1seq[t,b,:] @ out_w + out_b   (the 52-GFLOP bulk, fully parallel)
__global__ void k_logits(const float *ow, const float *ob, float *out)
{
    int t = blockIdx.y, n0 = blockIdx.x * 64;
    const float *A = g_H1seq + t * Bq * HIDq;
    gemm_core<128, 64, 16, 8, 8>(512,
        [&](int k, int mm) { return A[mm * HIDq + k]; },
        [&](int k, int nn) { int n = n0 + nn; return (n < VOCq) ? ow[k * VOCq + n] : 0.f; },
        [&](int mi, int nj, float v) {
            int n = n0 + nj;
            if (n < VOCq) out[((long)mi * Tq + t) * VOCq + n] = v + ob[n];
        });
}

__global__ void k_hidden(float *out)
{
    int i = blockIdx.x * blockDim.x + threadIdx.x;
    if (i < Bq * HIDq) { out[i] = g_H0[i]; out[Bq * HIDq + i] = g_H1[i]; }
}

// ---------------- launch ----------------
extern "C" void kernel_launch(void *const *d_in, const int *in_sizes, int n_in,
                              void *d_out, int out_size)
{
    const int   *tokens = (const int *)  d_in[0];
    const float *cnn    = (const float *)d_in[1];
    const float *emb    = (const float *)d_in[2];
    const float *wu0 = (const float *)d_in[3],  *bu0 = (const float *)d_in[4];
    const float *wr0 = (const float *)d_in[5],  *br0 = (const float *)d_in[6];
    const float *wc0 = (const float *)d_in[7],  *bc0 = (const float *)d_in[8];
    const float *wu1 = (const float *)d_in[9],  *bu1 = (const float *)d_in[10];
    const float *wr1 = (const float *)d_in[11], *br1 = (const float *)d_in[12];
    const float *wc1 = (const float *)d_in[13], *bc1 = (const float *)d_in[14];
    const float *ow  = (const float *)d_in[15], *ob  = (const float *)d_in[16];
    float *out = (float *)d_out;

    k_init<<<128, 512>>>();
    k_cnn  <<<dim3(8, 2, 3),  128>>>(cnn, wu0, wr0, wc0, bu0, br0, bc0);
    k_embed<<<dim3(8, 40, 3), 128>>>(tokens, emb, wu0, wr0, wc0);

    for (int t = 0; t < Tq; t++) {
        k_zr0<<<dim3(32, 4), 128>>>(t, wu0, wr0);
        k_h0 <<<dim3(16, 4), 128>>>(t, wc0);
        k_zr1<<<dim3(32, 4), 128>>>(wu1, wr1, bu1, br1);
        k_h1 <<<dim3(16, 4), 128>>>(t, wc1, bc1);
    }

    k_logits<<<dim3(157, 40), 128>>>(ow, ob, out);

    if (out_size >= Bq * Tq * VOCq + 2 * Bq * HIDq) {
        k_hidden<<<128, 512>>>(out + (long)Bq * Tq * VOCq);
    }
}

// round 3
// speedup vs baseline: 1.0457x; 1.0457x over previous
#include <cuda_runtime.h>

typedef unsigned long long ull;

#define NBLK 128
#define BH   65536          // 128*512
#define Tq   40
#define VOCq 10000

// ---------------- scratch (device globals; no allocation) ----------------
__device__ float g_P[3][Tq * BH];
__device__ float g_C[3][BH];
__device__ float g_H0B[2][BH];
__device__ float g_H1[BH];
__device__ float g_Z0[BH];
__device__ float g_RH0[BH];
__device__ float g_Z1[BH];
__device__ float g_RH1[BH];
__device__ float g_H1seq[Tq * BH];
__device__ unsigned g_cnt;

// ---------------- packed f32x2 helpers ----------------
__device__ __forceinline__ ull pk2(float x, float y) {
    ull r; asm("mov.b64 %0, {%1,%2};" : "=l"(r) : "f"(x), "f"(y)); return r;
}
__device__ __forceinline__ void upk2(ull v, float &x, float &y) {
    asm("mov.b64 {%0,%1}, %2;" : "=f"(x), "=f"(y) : "l"(v));
}
__device__ __forceinline__ void fma2(ull &c, ull a, ull b) {
    asm("fma.rn.f32x2 %0, %1, %2, %3;" : "=l"(c) : "l"(a), "l"(b), "l"(c));
}
__device__ __forceinline__ float sigm(float x) { return 1.f / (1.f + expf(-x)); }

// ---------------- grid-wide barrier ----------------
__device__ __forceinline__ void gridbar(unsigned &target) {
    __syncthreads();
    target += NBLK;
    if (threadIdx.x == 0) {
        asm volatile("red.release.gpu.add.u32 [%0], %1;" :: "l"(&g_cnt), "r"(1u) : "memory");
        unsigned v;
        do {
            asm volatile("ld.acquire.gpu.u32 %0, [%1];" : "=r"(v) : "l"(&g_cnt) : "memory");
        } while (v < target);
    }
    __syncthreads();
}

// ---------------- double-buffered SGEMM core (smem passed in) ----------------
// C[BM,BN] = sum_k aload(k,m)*wload(k,n); epilogue epi(mi,nj,val).
// Requires: sA >= 2*BK*(BM+1) floats, sW >= 2*BK*BN floats (16B aligned).
template<int BM, int BN, int BK, int TM, int TN, class AF, class WF, class EF>
__device__ __forceinline__ void core(float *sA, float *sW, int K,
                                     AF aload, WF wload, EF epi)
{
    constexpr int NT = BN / TN, MT = BM / TM, THREADS = NT * MT, TN2 = TN / 2;
    constexpr int ALD = BM * BK / THREADS, WLD = BK * BN / THREADS;
    constexpr int AS  = BM + 1;

    const int tid = threadIdx.x, tx = tid % NT, ty = tid / NT;
    __syncthreads();

    ull acc[TM][TN2];
#pragma unroll
    for (int i = 0; i < TM; i++)
#pragma unroll
        for (int j = 0; j < TN2; j++) acc[i][j] = 0ull;

#pragma unroll
    for (int j = 0; j < ALD; j++) {
        int idx = tid + j * THREADS;
        sA[(idx % BK) * AS + idx / BK] = aload(idx % BK, idx / BK);
    }
#pragma unroll
    for (int j = 0; j < WLD; j++) {
        int idx = tid + j * THREADS;
        sW[(idx / BN) * BN + idx % BN] = wload(idx / BN, idx % BN);
    }
    __syncthreads();

    const int niter = K / BK;
    for (int it = 0; it < niter; ++it) {
        float ra[ALD], rw[WLD];
        if (it + 1 < niter) {
            const int kb = (it + 1) * BK;
#pragma unroll
            for (int j = 0; j < ALD; j++) {
                int idx = tid + j * THREADS;
                ra[j] = aload(kb + idx % BK, idx / BK);
            }
#pragma unroll
            for (int j = 0; j < WLD; j++) {
                int idx = tid + j * THREADS;
                rw[j] = wload(kb + idx / BN, idx % BN);
            }
        }
        const float *A0 = sA + (it & 1) * BK * AS;
        const float *W0 = sW + (it & 1) * BK * BN;
#pragma unroll
        for (int kk = 0; kk < BK; kk++) {
            float a[TM]; ull b[TN2];
            const ull *wp = reinterpret_cast<const ull *>(W0 + kk * BN + tx * TN);
#pragma unroll
            for (int j = 0; j < TN2; j++) b[j] = wp[j];
#pragma unroll
            for (int i = 0; i < TM; i++) a[i] = A0[kk * AS + ty * TM + i];
#pragma unroll
            for (int i = 0; i < TM; i++) {
                ull a2 = pk2(a[i], a[i]);
#pragma unroll
                for (int j = 0; j < TN2; j++) fma2(acc[i][j], a2, b[j]);
            }
        }
        if (it + 1 < niter) {
            float *A1 = sA + ((it + 1) & 1) * BK * AS;
            float *W1 = sW + ((it + 1) & 1) * BK * BN;
#pragma unroll
            for (int j = 0; j < ALD; j++) {
                int idx = tid + j * THREADS;
                A1[(idx % BK) * AS + idx / BK] = ra[j];
            }
#pragma unroll
            for (int j = 0; j < WLD; j++) {
                int idx = tid + j * THREADS;
                W1[(idx / BN) * BN + idx % BN] = rw[j];
            }
            __syncthreads();
        }
    }

#pragma unroll
    for (int i = 0; i < TM; i++)
#pragma unroll
        for (int j = 0; j < TN2; j++) {
            float lo, hi; upk2(acc[i][j], lo, hi);
            epi(ty * TM + i, tx * TN + 2 * j,     lo);
            epi(ty * TM + i, tx * TN + 2 * j + 1, hi);
        }
}

// ---------------- recurrence phases (32x64 tiles, 256 threads) ----------------
// ZR-phase(t): tasks 0..63  = ZR1(t)  [valid for 0<=t<=39]
//              tasks 64..127= ZR0(t+1)[valid for t+1<=39]
__device__ void zrphase(int t, float *sA, float *sW,
    const float *wu0, const float *wr0,
    const float *wu1, const float *wr1, const float *bu1, const float *br1)
{
    int task = blockIdx.x;
    if (task < 64) {
        if (t < 0) return;
        int gate = task >> 5, id = task & 31;
        int m0 = (id >> 3) * 32, n0 = (id & 7) * 64;
        const float *W    = gate ? wr1 : wu1;
        const float *bias = gate ? br1 : bu1;
        const float *Hc   = g_H0B[t & 1];          // h0(t)
        core<32, 64, 32, 4, 2>(sA, sW, 1024,
            [&](int k, int m) { int r = m0 + m;
                return (k < 512) ? g_H1[r * 512 + k] : Hc[r * 512 + k - 512]; },
            [&](int k, int n) { return W[k * 512 + n0 + n]; },
            [&](int mi, int nj, float v) {
                int c = n0 + nj, idx = (m0 + mi) * 512 + c;
                float s = sigm(v + bias[c]);
                if (!gate) g_Z1[idx]  = s;
                else       g_RH1[idx] = s * g_H1[idx];
            });
    } else {
        int tn = t + 1;
        if (tn > 39) return;
        int t2 = task - 64;
        int gate = t2 >> 5, id = t2 & 31;
        int m0 = (id >> 3) * 32, n0 = (id & 7) * 64;
        const float *W  = gate ? wr0 : wu0;        // h-part = rows 0:512
        const float *Hp = g_H0B[t & 1];            // h0(t); t=-1 -> buffer 1 (zeros)
        const float *P  = g_P[gate] + (size_t)tn * BH;
        core<32, 64, 32, 4, 2>(sA, sW, 512,
            [&](int k, int m) { return Hp[(m0 + m) * 512 + k]; },
            [&](int k, int n) { return W[k * 512 + n0 + n]; },
            [&](int mi, int nj, float v) {
                int idx = (m0 + mi) * 512 + n0 + nj;
                float s = sigm(v + P[idx]);
                if (!gate) g_Z0[idx]  = s;
                else       g_RH0[idx] = s * Hp[idx];
            });
    }
}

// H-phase(t): tasks 0..31 = H1(t-1) [valid t>=1], tasks 32..63 = H0(t) [valid t<=39]
__device__ void hphase(int t, float *sA, float *sW,
    const float *wc0, const float *wc1, const float *bc1)
{
    int task = blockIdx.x;
    if (task < 32) {
        int tp = t - 1;
        if (tp < 0) return;
        int m0 = (task >> 3) * 32, n0 = (task & 7) * 64;
        const float *Hc = g_H0B[tp & 1];           // h0(tp)
        core<32, 64, 32, 4, 2>(sA, sW, 1024,
            [&](int k, int m) { int r = m0 + m;
                return (k < 512) ? g_RH1[r * 512 + k] : Hc[r * 512 + k - 512]; },
            [&](int k, int n) { return wc1[k * 512 + n0 + n]; },
            [&](int mi, int nj, float v) {
                int c = n0 + nj, idx = (m0 + mi) * 512 + c;
                float hh = tanhf(v + bc1[c]);
                float z  = g_Z1[idx];
                float hn = z * g_H1[idx] + (1.f - z) * hh;
                g_H1[idx] = hn;
                g_H1seq[(size_t)tp * BH + idx] = hn;
            });
    } else if (task < 64) {
        if (t > 39) return;
        int id = task - 32;
        int m0 = (id >> 3) * 32, n0 = (id & 7) * 64;
        const float *Hp = g_H0B[(t - 1) & 1];
        float       *Hn = g_H0B[t & 1];
        const float *P  = g_P[2] + (size_t)t * BH;
        core<32, 64, 32, 4, 2>(sA, sW, 512,
            [&](int k, int m) { return g_RH0[(m0 + m) * 512 + k]; },
            [&](int k, int n) { return wc0[k * 512 + n0 + n]; },
            [&](int mi, int nj, float v) {
                int idx = (m0 + mi) * 512 + n0 + nj;
                float hh = tanhf(v + P[idx]);
                float z  = g_Z0[idx];
                Hn[idx] = z * Hp[idx] + (1.f - z) * hh;
            });
    }
}

__global__ __launch_bounds__(256, 1) void k_recur(
    const float *wu0, const float *wr0, const float *wc0,
    const float *wu1, const float *bu1, const float *wr1, const float *br1,
    const float *wc1, const float *bc1)
{
    __shared__ float sA[2 * 32 * 33];
    __shared__ __align__(16) float sW[2 * 32 * 64];
    unsigned target = 0;

    zrphase(-1, sA, sW, wu0, wr0, wu1, wr1, bu1, br1);   // ZR0(0) only
    gridbar(target);
    for (int t = 0; t < Tq; t++) {
        hphase(t, sA, sW, wc0, wc1, bc1);                // H1(t-1) + H0(t)
        gridbar(target);
        zrphase(t, sA, sW, wu0, wr0, wu1, wr1, bu1, br1);// ZR1(t) + ZR0(t+1)
        gridbar(target);
    }
    hphase(Tq, sA, sW, wc0, wc1, bc1);                   // H1(39) only
}

// ---------------- setup / parallel kernels ----------------
__global__ void k_init() {
    int i = blockIdx.x * blockDim.x + threadIdx.x;
    if (i < BH) { g_H0B[1][i] = 0.f; g_H1[i] = 0.f; }
    if (i == 0) g_cnt = 0u;
}

// C_g = cnn @ Wg0[1024:1536] + b_g0
__global__ __launch_bounds__(256) void k_cnn(const float *cnn,
    const float *wu, const float *wr, const float *wc,
    const float *bu, const float *br, const float *bc)
{
    __shared__ float sA[2 * 16 * 129];
    __shared__ __align__(16) float sW[2 * 16 * 128];
    int g = blockIdx.z, n0 = blockIdx.x * 128;
    const float *W    = (g == 0 ? wu : g == 1 ? wr : wc) + 1024 * 512;
    const float *bias = (g == 0 ? bu : g == 1 ? br : bc);
    float *Cout = g_C[g];
    core<128, 128, 16, 8, 8>(sA, sW, 512,
        [&](int k, int m) { return cnn[m * 512 + k]; },
        [&](int k, int n) { return W[k * 512 + n0 + n]; },
        [&](int mi, int nj, float v) { Cout[mi * 512 + n0 + nj] = v + bias[n0 + nj]; });
}

// P_g[t] = emb[tokens[:,t]] @ Wg0[512:1024] + C_g
__global__ __launch_bounds__(256) void k_embed(const int *tokens, const float *emb,
    const float *wu, const float *wr, const float *wc)
{
    __shared__ float sA[2 * 16 * 129];
    __shared__ __align__(16) float sW[2 * 16 * 128];
    __shared__ int rowtok[128];
    int g = blockIdx.z, t = blockIdx.y, n0 = blockIdx.x * 128;
    if (threadIdx.x < 128) rowtok[threadIdx.x] = tokens[threadIdx.x * Tq + t];
    __syncthreads();
    const float *W  = (g == 0 ? wu : g == 1 ? wr : wc) + 512 * 512;
    const float *Cg = g_C[g];
    float *Pg = g_P[g] + (size_t)t * BH;
    core<128, 128, 16, 8, 8>(sA, sW, 512,
        [&](int k, int m) { return emb[(size_t)rowtok[m] * 512 + k]; },
        [&](int k, int n) { return W[k * 512 + n0 + n]; },
        [&](int mi, int nj, float v) {
            int idx = mi * 512 + n0 + nj;
            Pg[idx] = v + Cg[idx];
        });
}

// logits[b,t,:] = h1seq[t,b,:] @ out_w + out_b
__global__ __launch_bounds__(256) void k_logits(const float *ow, const float *ob, float *out)
{
    __shared__ float sA[2 * 16 * 129];
    __shared__ __align__(16) float sW[2 * 16 * 128];
    int t = blockIdx.y, n0 = blockIdx.x * 128;
    const float *A = g_H1seq + (size_t)t * BH;
    core<128, 128, 16, 8, 8>(sA, sW, 512,
        [&](int k, int m) { return A[m * 512 + k]; },
        [&](int k, int n) { int c = n0 + n; return (c < VOCq) ? ow[(size_t)k * VOCq + c] : 0.f; },
        [&](int mi, int nj, float v) {
            int c = n0 + nj;
            if (c < VOCq) out[((size_t)mi * Tq + t) * VOCq + c] = v + ob[c];
        });
}

__global__ void k_hidden(float *out)
{
    int i = blockIdx.x * blockDim.x + threadIdx.x;
    if (i < BH) { out[i] = g_H0B[1][i]; out[BH + i] = g_H1[i]; }
}

// ---------------- launch ----------------
extern "C" void kernel_launch(void *const *d_in, const int *in_sizes, int n_in,
                              void *d_out, int out_size)
{
    const int   *tokens = (const int *)  d_in[0];
    const float *cnn    = (const float *)d_in[1];
    const float *emb    = (const float *)d_in[2];
    const float *wu0 = (const float *)d_in[3],  *bu0 = (const float *)d_in[4];
    const float *wr0 = (const float *)d_in[5],  *br0 = (const float *)d_in[6];
    const float *wc0 = (const float *)d_in[7],  *bc0 = (const float *)d_in[8];
    const float *wu1 = (const float *)d_in[9],  *bu1 = (const float *)d_in[10];
    const float *wr1 = (const float *)d_in[11], *br1 = (const float *)d_in[12];
    const float *wc1 = (const float *)d_in[13], *bc1 = (const float *)d_in[14];
    const float *ow  = (const float *)d_in[15], *ob  = (const float *)d_in[16];
    float *out = (float *)d_out;

    k_init<<<128, 512>>>();
    k_cnn  <<<dim3(4, 1, 3),  256>>>(cnn, wu0, wr0, wc0, bu0, br0, bc0);
    k_embed<<<dim3(4, Tq, 3), 256>>>(tokens, emb, wu0, wr0, wc0);

    k_recur<<<NBLK, 256>>>(wu0, wr0, wc0, wu1, bu1, wr1, br1, wc1, bc1);

    k_logits<<<dim3(79, Tq), 256>>>(ow, ob, out);

    if (out_size >= Tq * 128 * VOCq + 2 * BH) {
        k_hidden<<<128, 512>>>(out + (size_t)Tq * 128 * VOCq);
    }
}